// round 7
// baseline (speedup 1.0000x reference)
#include <cuda_runtime.h>
#include <cstdint>
#include <math.h>
#include <mma.h>
using namespace nvcuda;

// Problem: B=4,S=2048 -> T=8192 tokens, H=1024, E=8, top-2.
#define Tt  8192
#define Hh  1024
#define HD2 2048
#define NE  8

#define TM 128
#define TN 256
#define TK 32            // K floats per stage (= 128 B/row)
#define LDS_AB 36        // padded row: 36 floats = 144 B
#define LDS_C  264       // C staging row (boundary path only)

#define SA_BYTES  (TM * LDS_AB * 4)        // 18432
#define SB_BYTES  (TN * LDS_AB * 4)        // 36864
#define STAGE     (SA_BYTES + SB_BYTES)    // 55296
#define NSTAGE    3
#define SMEM_BYTES (NSTAGE * STAGE)        // 165888

// ---------------- device scratch (alloc-free rule) ----------------
__device__ int    g_cnt[NE];
__device__ int    g_off[NE];
__device__ int    g_tok[NE * Tt];
__device__ int4   g_info[Tt];                    // e0,p0,e1,p1
__device__ float2 g_wts[Tt];                     // gate weights
__device__ float  g_xc [(size_t)Tt * Hh];        // tf32-rounded x        (32MB)
__device__ float  g_w1c[(size_t)NE * HD2 * Hh];  // tf32-rounded w1       (64MB)
__device__ float  g_w2c[(size_t)NE * Hh * HD2];  // tf32-rounded w2       (64MB)
__device__ float  g_hbuf[(size_t)2 * Tt * HD2];  // gelu(x@w1^T), rounded (128MB)
__device__ float  g_ybuf[(size_t)2 * Tt * Hh];   // y per slot            (64MB)

// ---------------- helpers ----------------
__device__ __forceinline__ uint32_t smem_u32(const void* p) {
    uint32_t a;
    asm("{ .reg .u64 t; cvta.to.shared.u64 t, %1; cvt.u32.u64 %0, t; }" : "=r"(a) : "l"(p));
    return a;
}
__device__ __forceinline__ uint32_t f2tf32(float v) {
    uint32_t o;
    asm("cvt.rna.tf32.f32 %0, %1;" : "=r"(o) : "f"(v));
    return o;
}
__device__ __forceinline__ float gelu_f(float v) {
    return 0.5f * v * (1.0f + erff(v * 0.70710678118654752f));
}
#define CPA(dst, src, n) \
    asm volatile("cp.async.cg.shared.global [%0], [%1], 16, %2;" \
                 :: "r"(dst), "l"(src), "r"(n) : "memory")
#define CPC() asm volatile("cp.async.commit_group;" ::: "memory")
#define CPW(N) asm volatile("cp.async.wait_group %0;" :: "n"(N) : "memory")

// ---------------------------------------------------------------------------
// Prepass: round fp32 -> tf32-in-fp32 (removes all cvt from GEMM hot loops)
// ---------------------------------------------------------------------------
__global__ __launch_bounds__(256) void cvt_tf32_kernel(const float4* __restrict__ s,
                                                       uint4* __restrict__ d, int n4) {
    int i = blockIdx.x * 256 + threadIdx.x;
    if (i < n4) {
        float4 v = s[i];
        uint4 u = { f2tf32(v.x), f2tf32(v.y), f2tf32(v.z), f2tf32(v.w) };
        d[i] = u;
    }
}

// ---------------------------------------------------------------------------
// Router: one warp per token; logits, top-2, softmax, expert lists + meta.
// ---------------------------------------------------------------------------
__global__ __launch_bounds__(256) void router_kernel(const float* __restrict__ x,
                                                     const float* __restrict__ rw) {
    __shared__ float s_rw[NE * Hh];
    for (int i = threadIdx.x; i < NE * Hh; i += 256) s_rw[i] = rw[i];
    __syncthreads();

    int warp = threadIdx.x >> 5, lane = threadIdx.x & 31;
    int t = blockIdx.x * 8 + warp;

    float xv[32];
    const float* xr = x + (size_t)t * Hh;
#pragma unroll
    for (int i = 0; i < 32; i++) xv[i] = xr[i * 32 + lane];

    float logit[NE];
#pragma unroll
    for (int e = 0; e < NE; e++) {
        float p = 0.f;
        const float* w = s_rw + e * Hh;
#pragma unroll
        for (int i = 0; i < 32; i++) p += xv[i] * w[i * 32 + lane];
#pragma unroll
        for (int o = 16; o > 0; o >>= 1) p += __shfl_xor_sync(0xffffffffu, p, o);
        logit[e] = p;
    }

    if (lane == 0) {
        int e0 = 0; float v0 = logit[0];
#pragma unroll
        for (int e = 1; e < NE; e++) if (logit[e] > v0) { v0 = logit[e]; e0 = e; }
        int e1 = -1; float v1 = -3.4e38f;
#pragma unroll
        for (int e = 0; e < NE; e++) if (e != e0 && logit[e] > v1) { v1 = logit[e]; e1 = e; }
        float w0 = 1.f / (1.f + expf(v1 - v0));
        float w1v = 1.f - w0;
        int p0 = atomicAdd(&g_cnt[e0], 1);
        g_tok[e0 * Tt + p0] = t;
        int p1 = atomicAdd(&g_cnt[e1], 1);
        g_tok[e1 * Tt + p1] = t;
        g_info[t] = make_int4(e0, p0, e1, p1);
        g_wts[t] = make_float2(w0, w1v);
    }
}

__global__ void offsets_kernel() {
    if (threadIdx.x == 0) {
        int s = 0;
#pragma unroll
        for (int e = 0; e < NE; e++) { g_off[e] = s; s += g_cnt[e]; }
    }
}

// ---------------------------------------------------------------------------
// Grouped GEMM (wmma tf32): D[128,256] = A @ B^T, A gathered.
// 8 warps = 2x4 grid of 64x64 warp tiles (16 independent accumulators/warp).
// 3-stage cp.async pipeline, 1 bar/chunk. Direct-from-fragment epilogue for
// full tiles; smem-masked path only for the boundary tile.
// FIRST: A = g_xc rows by g_tok (K=1024); out = tf32(gelu(.)) -> g_hbuf
// else : A = g_hbuf rows by slot (K=2048); out = raw          -> g_ybuf
// ---------------------------------------------------------------------------
template<int KTOT, bool FIRST>
__global__ __launch_bounds__(256, 1) void moe_gemm_kernel(const float* __restrict__ Abase,
                                                          const float* __restrict__ Wb,
                                                          float* __restrict__ Out) {
    int e = blockIdx.z;
    int cnt = g_cnt[e];
    int m0 = blockIdx.x * TM;
    if (m0 >= cnt) return;
    int n0 = blockIdx.y * TN;
    const int LDO = FIRST ? HD2 : Hh;

    extern __shared__ char smem[];
    uint32_t sbase = smem_u32(smem);
    int tid = threadIdx.x;
    int wid = tid >> 5;
    int wm = wid & 1;            // 2 M sub-blocks of 64
    int wn = wid >> 1;           // 4 N sub-blocks of 64

    // Per-thread cp.async slots: A = 128 rows x 8 x16B (4/thread),
    //                            B = 256 rows x 8 x16B (8/thread)
    const float* aptr[4]; uint32_t anv[4], soffA[4];
    const float* bptr[8]; uint32_t soffB[8];
    const float* Bg = Wb + (size_t)e * (size_t)KTOT * (FIRST ? HD2 : Hh);
#pragma unroll
    for (int i = 0; i < 4; i++) {
        int lin = tid + i * 256;              // 0..1023
        int r = lin >> 3;                     // 0..127
        int c4 = (lin & 7) * 4;               // float col 0..28
        bool av = (m0 + r) < cnt;
        anv[i] = av ? 16u : 0u;
        int row;
        if (FIRST) row = av ? g_tok[e * Tt + m0 + r] : 0;
        else       row = g_off[e] + m0 + (av ? r : 0);
        aptr[i] = Abase + (size_t)row * KTOT + c4;
        soffA[i] = (uint32_t)(r * (LDS_AB * 4) + c4 * 4);
    }
#pragma unroll
    for (int i = 0; i < 8; i++) {
        int lin = tid + i * 256;              // 0..2047
        int r = lin >> 3;                     // 0..255
        int c4 = (lin & 7) * 4;
        bptr[i] = Bg + (size_t)(n0 + r) * KTOT + c4;
        soffB[i] = (uint32_t)(SA_BYTES + r * (LDS_AB * 4) + c4 * 4);
    }

    wmma::fragment<wmma::accumulator, 16, 16, 8, float> cf[4][4];
#pragma unroll
    for (int i = 0; i < 4; i++)
#pragma unroll
        for (int j = 0; j < 4; j++) wmma::fill_fragment(cf[i][j], 0.0f);

    const int S = KTOT / TK;

    // prologue: stages 0,1
#pragma unroll
    for (int s = 0; s < 2; s++) {
        uint32_t sb = sbase + s * STAGE;
#pragma unroll
        for (int i = 0; i < 4; i++) CPA(sb + soffA[i], aptr[i] + s * TK, anv[i]);
#pragma unroll
        for (int i = 0; i < 8; i++) CPA(sb + soffB[i], bptr[i] + s * TK, 16u);
        CPC();
    }

    int buf = 0;
    for (int s = 0; s < S; s++) {
        if (s + 1 < S) { CPW(1); } else { CPW(0); }
        __syncthreads();
        if (s + 2 < S) {
            int b2 = buf + 2; if (b2 >= NSTAGE) b2 -= NSTAGE;
            uint32_t sb = sbase + b2 * STAGE;
            int k0 = (s + 2) * TK;
#pragma unroll
            for (int i = 0; i < 4; i++) CPA(sb + soffA[i], aptr[i] + k0, anv[i]);
#pragma unroll
            for (int i = 0; i < 8; i++) CPA(sb + soffB[i], bptr[i] + k0, 16u);
            CPC();
        }
        const float* sA = (const float*)(smem + buf * STAGE);
        const float* sB = (const float*)(smem + buf * STAGE + SA_BYTES);
#pragma unroll
        for (int kk = 0; kk < 4; kk++) {
            wmma::fragment<wmma::matrix_a, 16, 16, 8, wmma::precision::tf32, wmma::row_major> af[4];
            wmma::fragment<wmma::matrix_b, 16, 16, 8, wmma::precision::tf32, wmma::col_major> bf[4];
#pragma unroll
            for (int i = 0; i < 4; i++)
                wmma::load_matrix_sync(af[i], sA + (wm * 64 + i * 16) * LDS_AB + kk * 8, LDS_AB);
#pragma unroll
            for (int j = 0; j < 4; j++)
                wmma::load_matrix_sync(bf[j], sB + (wn * 64 + j * 16) * LDS_AB + kk * 8, LDS_AB);
#pragma unroll
            for (int i = 0; i < 4; i++)
#pragma unroll
                for (int j = 0; j < 4; j++)
                    wmma::mma_sync(cf[i][j], af[i], bf[j], cf[i][j]);
        }
        if (++buf == NSTAGE) buf = 0;
    }

    int base_slot = g_off[e] + m0;

    // In-register transform (gelu + tf32 round for GEMM1 output)
    if (FIRST) {
#pragma unroll
        for (int i = 0; i < 4; i++)
#pragma unroll
            for (int j = 0; j < 4; j++)
#pragma unroll
                for (int t = 0; t < 8; t++)
                    cf[i][j].x[t] = __uint_as_float(f2tf32(gelu_f(cf[i][j].x[t])));
    }

    if (m0 + TM <= cnt) {
        // Full tile: store fragments directly to gmem.
#pragma unroll
        for (int i = 0; i < 4; i++)
#pragma unroll
            for (int j = 0; j < 4; j++)
                wmma::store_matrix_sync(Out + (size_t)(base_slot + wm * 64 + i * 16) * LDO
                                            + n0 + wn * 64 + j * 16,
                                        cf[i][j], LDO, wmma::mem_row_major);
    } else {
        // Boundary tile: stage via smem, masked row writes.
        __syncthreads();
        float* sC = (float*)smem;
#pragma unroll
        for (int i = 0; i < 4; i++)
#pragma unroll
            for (int j = 0; j < 4; j++)
                wmma::store_matrix_sync(sC + (wm * 64 + i * 16) * LDS_C + wn * 64 + j * 16,
                                        cf[i][j], LDS_C, wmma::mem_row_major);
        __syncthreads();
#pragma unroll
        for (int it = 0; it < 32; it++) {
            int lin = tid + it * 256;          // 128 rows x 64 float4
            int r = lin >> 6;
            int c4 = (lin & 63) << 2;
            if (m0 + r < cnt) {
                const float* sp = sC + r * LDS_C + c4;
                float4 v = { sp[0], sp[1], sp[2], sp[3] };
                *(float4*)(Out + (size_t)(base_slot + r) * LDO + n0 + c4) = v;
            }
        }
    }
}

// ---------------------------------------------------------------------------
// Combine: out[t] = w0 * y[slot0] + w1 * y[slot1]   (deterministic, no atomics)
// ---------------------------------------------------------------------------
__global__ __launch_bounds__(256) void combine_kernel(float* __restrict__ out) {
    int t = blockIdx.x;
    int c = threadIdx.x;
    int4 mi = g_info[t];
    float2 gw = g_wts[t];
    size_t s0 = (size_t)(g_off[mi.x] + mi.y) * Hh + c * 4;
    size_t s1 = (size_t)(g_off[mi.z] + mi.w) * Hh + c * 4;
    float4 a = *(const float4*)(g_ybuf + s0);
    float4 b = *(const float4*)(g_ybuf + s1);
    float4 o;
    o.x = gw.x * a.x + gw.y * b.x;
    o.y = gw.x * a.y + gw.y * b.y;
    o.z = gw.x * a.z + gw.y * b.z;
    o.w = gw.x * a.w + gw.y * b.w;
    *(float4*)(out + (size_t)t * Hh + c * 4) = o;
}

// ---------------------------------------------------------------------------
extern "C" void kernel_launch(void* const* d_in, const int* in_sizes, int n_in,
                              void* d_out, int out_size) {
    const float* x  = (const float*)d_in[0];
    const float* rw = (const float*)d_in[1];
    const float* w1 = (const float*)d_in[2];
    const float* w2 = (const float*)d_in[3];
    float* out = (float*)d_out;

    void* cntp = nullptr; cudaGetSymbolAddress(&cntp, g_cnt);
    cudaMemsetAsync(cntp, 0, sizeof(int) * NE);

    void* xc = nullptr;  cudaGetSymbolAddress(&xc,  g_xc);
    void* w1c = nullptr; cudaGetSymbolAddress(&w1c, g_w1c);
    void* w2c = nullptr; cudaGetSymbolAddress(&w2c, g_w2c);
    void* hb = nullptr;  cudaGetSymbolAddress(&hb,  g_hbuf);
    void* yb = nullptr;  cudaGetSymbolAddress(&yb,  g_ybuf);

    // Prepass: tf32-round x, w1, w2
    {
        int n4x = (Tt * Hh) / 4;
        int n4w = (NE * HD2 * Hh) / 4;
        cvt_tf32_kernel<<<(n4x + 255) / 256, 256>>>((const float4*)x,  (uint4*)xc,  n4x);
        cvt_tf32_kernel<<<(n4w + 255) / 256, 256>>>((const float4*)w1, (uint4*)w1c, n4w);
        cvt_tf32_kernel<<<(n4w + 255) / 256, 256>>>((const float4*)w2, (uint4*)w2c, n4w);
    }

    router_kernel<<<Tt / 8, 256>>>(x, rw);
    offsets_kernel<<<1, 32>>>();

    cudaFuncSetAttribute(moe_gemm_kernel<Hh, true>,
                         cudaFuncAttributeMaxDynamicSharedMemorySize, SMEM_BYTES);
    cudaFuncSetAttribute(moe_gemm_kernel<HD2, false>,
                         cudaFuncAttributeMaxDynamicSharedMemorySize, SMEM_BYTES);

    dim3 g1(Tt / TM, HD2 / TN, NE);   // (64, 8, 8): GEMM1  N=2048, K=1024
    dim3 g2(Tt / TM, Hh  / TN, NE);   // (64, 4, 8): GEMM2  N=1024, K=2048
    moe_gemm_kernel<Hh,  true ><<<g1, 256, SMEM_BYTES>>>((const float*)xc, (const float*)w1c, (float*)hb);
    moe_gemm_kernel<HD2, false><<<g2, 256, SMEM_BYTES>>>((const float*)hb, (const float*)w2c, (float*)yb);

    combine_kernel<<<Tt, 256>>>(out);
}

// round 8
// speedup vs baseline: 1.5635x; 1.5635x over previous
#include <cuda_runtime.h>
#include <cstdint>
#include <math.h>

// Problem: B=4,S=2048 -> T=8192 tokens, H=1024, E=8, top-2.
#define Tt  8192
#define Hh  1024
#define HD2 2048
#define NE  8

#define TM 128
#define TN 128
#define TK 32            // K floats per stage (= 128 B/row)
#define LDS_AB 36        // padded row: 36 floats = 144 B
#define LDS_C  132

#define SA_BYTES  (128 * LDS_AB * 4)      // 18432
#define STAGE     (2 * SA_BYTES)          // 36864 (A tile + B tile)
#define NSTAGE    3
#define SMEM_BYTES (NSTAGE * STAGE)       // 110592  (x2 CTAs = 221184 <= 228KB)

#include <mma.h>
using namespace nvcuda;

// ---------------- device scratch (alloc-free rule) ----------------
__device__ int    g_cnt[NE];
__device__ int    g_off[NE];
__device__ int    g_tok[NE * Tt];
__device__ int4   g_info[Tt];                    // e0,p0,e1,p1
__device__ float2 g_wts[Tt];                     // gate weights
__device__ float  g_xc [(size_t)Tt * Hh];        // tf32-rounded x        (32MB)
__device__ float  g_w1c[(size_t)NE * HD2 * Hh];  // tf32-rounded w1       (64MB)
__device__ float  g_w2c[(size_t)NE * Hh * HD2];  // tf32-rounded w2       (64MB)
__device__ float  g_hbuf[(size_t)2 * Tt * HD2];  // gelu(x@w1^T), rounded (128MB)
__device__ float  g_ybuf[(size_t)2 * Tt * Hh];   // y per slot            (64MB)

// ---------------- helpers ----------------
__device__ __forceinline__ uint32_t smem_u32(const void* p) {
    uint32_t a;
    asm("{ .reg .u64 t; cvta.to.shared.u64 t, %1; cvt.u32.u64 %0, t; }" : "=r"(a) : "l"(p));
    return a;
}
__device__ __forceinline__ uint32_t f2tf32(float v) {
    uint32_t o;
    asm("cvt.rna.tf32.f32 %0, %1;" : "=r"(o) : "f"(v));
    return o;
}
__device__ __forceinline__ float gelu_f(float v) {
    return 0.5f * v * (1.0f + erff(v * 0.70710678118654752f));
}
#define CPA(dst, src, n) \
    asm volatile("cp.async.cg.shared.global [%0], [%1], 16, %2;" \
                 :: "r"(dst), "l"(src), "r"(n) : "memory")
#define CPC() asm volatile("cp.async.commit_group;" ::: "memory")
#define CPW(N) asm volatile("cp.async.wait_group %0;" :: "n"(N) : "memory")

// ---------------------------------------------------------------------------
// Prepass: round fp32 -> tf32-in-fp32 (removes all cvt from GEMM hot loops)
// ---------------------------------------------------------------------------
__global__ __launch_bounds__(256) void cvt_tf32_kernel(const float4* __restrict__ s,
                                                       uint4* __restrict__ d, int n4) {
    int i = blockIdx.x * 256 + threadIdx.x;
    if (i < n4) {
        float4 v = s[i];
        uint4 u = { f2tf32(v.x), f2tf32(v.y), f2tf32(v.z), f2tf32(v.w) };
        d[i] = u;
    }
}

// ---------------------------------------------------------------------------
// Router: one warp per token; logits, top-2, softmax, expert lists + meta.
// ---------------------------------------------------------------------------
__global__ __launch_bounds__(256) void router_kernel(const float* __restrict__ x,
                                                     const float* __restrict__ rw) {
    __shared__ float s_rw[NE * Hh];
    for (int i = threadIdx.x; i < NE * Hh; i += 256) s_rw[i] = rw[i];
    __syncthreads();

    int warp = threadIdx.x >> 5, lane = threadIdx.x & 31;
    int t = blockIdx.x * 8 + warp;

    float xv[32];
    const float* xr = x + (size_t)t * Hh;
#pragma unroll
    for (int i = 0; i < 32; i++) xv[i] = xr[i * 32 + lane];

    float logit[NE];
#pragma unroll
    for (int e = 0; e < NE; e++) {
        float p = 0.f;
        const float* w = s_rw + e * Hh;
#pragma unroll
        for (int i = 0; i < 32; i++) p += xv[i] * w[i * 32 + lane];
#pragma unroll
        for (int o = 16; o > 0; o >>= 1) p += __shfl_xor_sync(0xffffffffu, p, o);
        logit[e] = p;
    }

    if (lane == 0) {
        int e0 = 0; float v0 = logit[0];
#pragma unroll
        for (int e = 1; e < NE; e++) if (logit[e] > v0) { v0 = logit[e]; e0 = e; }
        int e1 = -1; float v1 = -3.4e38f;
#pragma unroll
        for (int e = 0; e < NE; e++) if (e != e0 && logit[e] > v1) { v1 = logit[e]; e1 = e; }
        float w0 = 1.f / (1.f + expf(v1 - v0));
        float w1v = 1.f - w0;
        int p0 = atomicAdd(&g_cnt[e0], 1);
        g_tok[e0 * Tt + p0] = t;
        int p1 = atomicAdd(&g_cnt[e1], 1);
        g_tok[e1 * Tt + p1] = t;
        g_info[t] = make_int4(e0, p0, e1, p1);
        g_wts[t] = make_float2(w0, w1v);
    }
}

__global__ void offsets_kernel() {
    if (threadIdx.x == 0) {
        int s = 0;
#pragma unroll
        for (int e = 0; e < NE; e++) { g_off[e] = s; s += g_cnt[e]; }
    }
}

// ---------------------------------------------------------------------------
// Grouped GEMM (wmma tf32 m16n16k8): D[128,128] = A @ B^T, A gathered.
// 3-stage cp.async pipeline, 1 bar/chunk. 8 warps = 4x2 grid of 32x64 tiles.
// __launch_bounds__(256,2): 2 CTAs/SM (16 warps = 4/SMSP) for latency hiding.
// FIRST: A = g_xc rows by g_tok (K=1024); out = tf32(gelu(.)) -> g_hbuf
// else : A = g_hbuf rows by slot (K=2048); out = raw          -> g_ybuf
// ---------------------------------------------------------------------------
template<int KTOT, bool FIRST>
__global__ __launch_bounds__(256, 2) void moe_gemm_kernel(const float* __restrict__ Abase,
                                                          const float* __restrict__ Wb,
                                                          float* __restrict__ Out) {
    int e = blockIdx.z;
    int cnt = g_cnt[e];
    int m0 = blockIdx.x * TM;
    if (m0 >= cnt) return;
    int n0 = blockIdx.y * TN;

    extern __shared__ char smem[];
    uint32_t sbase = smem_u32(smem);
    int tid = threadIdx.x;
    int wid = tid >> 5;
    int wm = wid & 3, wn = wid >> 2;

    // Per-thread load slots: A = 128x8 float4, B = 128x8 float4 (4 each /thread)
    const float* aptr[4]; uint32_t anv[4], soffA[4];
    const float* bptr[4]; uint32_t soffB[4];
    const float* Bg = Wb + (size_t)e * (size_t)KTOT * (FIRST ? HD2 : Hh);
#pragma unroll
    for (int i = 0; i < 4; i++) {
        int lin = tid + i * 256;              // 0..1023
        int r = lin >> 3;                     // 0..127
        int c4 = (lin & 7) * 4;               // float col 0,4,...,28
        bool av = (m0 + r) < cnt;
        anv[i] = av ? 16u : 0u;
        int row;
        if (FIRST) row = av ? g_tok[e * Tt + m0 + r] : 0;
        else       row = g_off[e] + m0 + (av ? r : 0);
        aptr[i] = Abase + (size_t)row * KTOT + c4;
        bptr[i] = Bg + (size_t)(n0 + r) * KTOT + c4;
        soffA[i] = (uint32_t)(r * (LDS_AB * 4) + c4 * 4);
        soffB[i] = soffA[i] + SA_BYTES;
    }

    wmma::fragment<wmma::accumulator, 16, 16, 8, float> cf[2][4];
#pragma unroll
    for (int i = 0; i < 2; i++)
#pragma unroll
        for (int j = 0; j < 4; j++) wmma::fill_fragment(cf[i][j], 0.0f);

    const int S = KTOT / TK;

    // prologue: stages 0,1
#pragma unroll
    for (int s = 0; s < 2; s++) {
        uint32_t sb = sbase + s * STAGE;
#pragma unroll
        for (int i = 0; i < 4; i++) CPA(sb + soffA[i], aptr[i] + s * TK, anv[i]);
#pragma unroll
        for (int i = 0; i < 4; i++) CPA(sb + soffB[i], bptr[i] + s * TK, 16u);
        CPC();
    }

    int buf = 0;
    for (int s = 0; s < S; s++) {
        if (s + 1 < S) { CPW(1); } else { CPW(0); }
        __syncthreads();
        // issue stage s+2 (its buffer was consumed at iter s-1; bar above makes it safe)
        if (s + 2 < S) {
            int b2 = buf + 2; if (b2 >= NSTAGE) b2 -= NSTAGE;
            uint32_t sb = sbase + b2 * STAGE;
            int k0 = (s + 2) * TK;
#pragma unroll
            for (int i = 0; i < 4; i++) CPA(sb + soffA[i], aptr[i] + k0, anv[i]);
#pragma unroll
            for (int i = 0; i < 4; i++) CPA(sb + soffB[i], bptr[i] + k0, 16u);
            CPC();
        }
        const float* sA = (const float*)(smem + buf * STAGE);
        const float* sB = (const float*)(smem + buf * STAGE + SA_BYTES);
#pragma unroll
        for (int kk = 0; kk < 4; kk++) {
            wmma::fragment<wmma::matrix_a, 16, 16, 8, wmma::precision::tf32, wmma::row_major> af[2];
            wmma::fragment<wmma::matrix_b, 16, 16, 8, wmma::precision::tf32, wmma::col_major> bf[4];
#pragma unroll
            for (int i = 0; i < 2; i++)
                wmma::load_matrix_sync(af[i], sA + (wm * 32 + i * 16) * LDS_AB + kk * 8, LDS_AB);
#pragma unroll
            for (int j = 0; j < 4; j++)
                wmma::load_matrix_sync(bf[j], sB + (wn * 64 + j * 16) * LDS_AB + kk * 8, LDS_AB);
#pragma unroll
            for (int i = 0; i < 2; i++)
#pragma unroll
                for (int j = 0; j < 4; j++)
                    wmma::mma_sync(cf[i][j], af[i], bf[j], cf[i][j]);
        }
        if (++buf == NSTAGE) buf = 0;
    }

    // Epilogue via smem C staging (reuses pipeline buffers)
    __syncthreads();
    float* sC = (float*)smem;
#pragma unroll
    for (int i = 0; i < 2; i++)
#pragma unroll
        for (int j = 0; j < 4; j++)
            wmma::store_matrix_sync(sC + (wm * 32 + i * 16) * LDS_C + wn * 64 + j * 16,
                                    cf[i][j], LDS_C, wmma::mem_row_major);
    __syncthreads();

    int base_slot = g_off[e] + m0;
#pragma unroll
    for (int it = 0; it < 16; it++) {
        int lin = tid + it * 256;            // 128 rows x 32 float4
        int r = lin >> 5;
        int c4 = (lin & 31) << 2;
        if (m0 + r < cnt) {
            const float* sp = sC + r * LDS_C + c4;
            float4 v;
            if (FIRST) {   // round to tf32 here so GEMM2's A needs no cvt
                v.x = __uint_as_float(f2tf32(gelu_f(sp[0])));
                v.y = __uint_as_float(f2tf32(gelu_f(sp[1])));
                v.z = __uint_as_float(f2tf32(gelu_f(sp[2])));
                v.w = __uint_as_float(f2tf32(gelu_f(sp[3])));
            } else {
                v.x = sp[0]; v.y = sp[1]; v.z = sp[2]; v.w = sp[3];
            }
            *(float4*)(Out + (size_t)(base_slot + r) * (FIRST ? HD2 : Hh) + n0 + c4) = v;
        }
    }
}

// ---------------------------------------------------------------------------
// Combine: out[t] = w0 * y[slot0] + w1 * y[slot1]   (deterministic, no atomics)
// ---------------------------------------------------------------------------
__global__ __launch_bounds__(256) void combine_kernel(float* __restrict__ out) {
    int t = blockIdx.x;
    int c = threadIdx.x;
    int4 mi = g_info[t];
    float2 gw = g_wts[t];
    size_t s0 = (size_t)(g_off[mi.x] + mi.y) * Hh + c * 4;
    size_t s1 = (size_t)(g_off[mi.z] + mi.w) * Hh + c * 4;
    float4 a = *(const float4*)(g_ybuf + s0);
    float4 b = *(const float4*)(g_ybuf + s1);
    float4 o;
    o.x = gw.x * a.x + gw.y * b.x;
    o.y = gw.x * a.y + gw.y * b.y;
    o.z = gw.x * a.z + gw.y * b.z;
    o.w = gw.x * a.w + gw.y * b.w;
    *(float4*)(out + (size_t)t * Hh + c * 4) = o;
}

// ---------------------------------------------------------------------------
extern "C" void kernel_launch(void* const* d_in, const int* in_sizes, int n_in,
                              void* d_out, int out_size) {
    const float* x  = (const float*)d_in[0];
    const float* rw = (const float*)d_in[1];
    const float* w1 = (const float*)d_in[2];
    const float* w2 = (const float*)d_in[3];
    float* out = (float*)d_out;

    void* cntp = nullptr; cudaGetSymbolAddress(&cntp, g_cnt);
    cudaMemsetAsync(cntp, 0, sizeof(int) * NE);

    void* xc = nullptr;  cudaGetSymbolAddress(&xc,  g_xc);
    void* w1c = nullptr; cudaGetSymbolAddress(&w1c, g_w1c);
    void* w2c = nullptr; cudaGetSymbolAddress(&w2c, g_w2c);
    void* hb = nullptr;  cudaGetSymbolAddress(&hb,  g_hbuf);
    void* yb = nullptr;  cudaGetSymbolAddress(&yb,  g_ybuf);

    // Prepass: tf32-round x, w1, w2 (one pass; removes cvt from GEMM mainloops)
    {
        int n4x = (Tt * Hh) / 4;                    // 2,097,152
        int n4w = (NE * HD2 * Hh) / 4;              // 4,194,304
        cvt_tf32_kernel<<<(n4x + 255) / 256, 256>>>((const float4*)x,  (uint4*)xc,  n4x);
        cvt_tf32_kernel<<<(n4w + 255) / 256, 256>>>((const float4*)w1, (uint4*)w1c, n4w);
        cvt_tf32_kernel<<<(n4w + 255) / 256, 256>>>((const float4*)w2, (uint4*)w2c, n4w);
    }

    router_kernel<<<Tt / 8, 256>>>(x, rw);
    offsets_kernel<<<1, 32>>>();

    cudaFuncSetAttribute(moe_gemm_kernel<Hh, true>,
                         cudaFuncAttributeMaxDynamicSharedMemorySize, SMEM_BYTES);
    cudaFuncSetAttribute(moe_gemm_kernel<HD2, false>,
                         cudaFuncAttributeMaxDynamicSharedMemorySize, SMEM_BYTES);

    dim3 g1(Tt / TM, HD2 / TN, NE);   // (64, 16, 8): GEMM1  N=2048, K=1024
    dim3 g2(Tt / TM, Hh  / TN, NE);   // (64,  8, 8): GEMM2  N=1024, K=2048
    moe_gemm_kernel<Hh,  true ><<<g1, 256, SMEM_BYTES>>>((const float*)xc, (const float*)w1c, (float*)hb);
    moe_gemm_kernel<HD2, false><<<g2, 256, SMEM_BYTES>>>((const float*)hb, (const float*)w2c, (float*)yb);

    combine_kernel<<<Tt, 256>>>(out);
}